// round 15
// baseline (speedup 1.0000x reference)
#include <cuda_runtime.h>

#define NPTS 16384
#define MPTS 4096
#define KNN  16
#define NCELL 512          // 8x8x8 grid, Morton-ordered (locality sort only)

// ---------------- scratch (device globals; no allocation) ----------------
__device__ float  g_x1[NPTS * 32];
__device__ float4 g_pw[NPTS];       // x, y, z, |p|^2
__device__ int    g_idx[MPTS];
__device__ float4 g_np[MPTS];
__device__ int    g_knn[MPTS * KNN];
__device__ float  g_x2[MPTS * 64];
__device__ float  g_f2[MPTS * 32];
// sort scratch
__device__ float4 g_sp[NPTS];                 // sorted: x,y,z, orig idx bits
__device__ int    g_cellstart[NCELL + 1];
__device__ int    g_rank[NPTS];
__device__ int    g_ptcell[NPTS];

__device__ __forceinline__ unsigned redux_max_u32(unsigned v) {
    unsigned r;
    asm("redux.sync.max.u32 %0, %1, 0xffffffff;" : "=r"(r) : "r"(v));
    return r;
}
__device__ __forceinline__ unsigned redux_min_u32(unsigned v) {
    unsigned r;
    asm("redux.sync.min.u32 %0, %1, 0xffffffff;" : "=r"(r) : "r"(v));
    return r;
}
#define NBAR_SYNC(id)   asm volatile("bar.sync %0, 1024;" :: "r"(id) : "memory")
#define NBAR_ARRIVE(id) asm volatile("bar.arrive %0, 1024;" :: "r"(id) : "memory")

// XLA-matching primitives (DO NOT CHANGE: bit-exactness of selections)
__device__ __forceinline__ float sq3_fma(float x, float y, float z) {
    return __fmaf_rn(z, z, __fmaf_rn(y, y, __fmul_rn(x, x)));
}
__device__ __forceinline__ float dot3_fma(float ax, float ay, float az,
                                          float bx, float by, float bz) {
    return __fmaf_rn(az, bz, __fmaf_rn(ay, by, __fmul_rn(ax, bx)));
}
__device__ __forceinline__ float sqdist_expand(float aw, float dot, float bw) {
    return __fadd_rn(__fsub_rn(aw, __fmul_rn(2.0f, dot)), bw);
}

// 16-slot lex-max tournament (max dmin, tie -> min orig idx); excl slot -> 0
__device__ __forceinline__ void tourney16(const float* dmin, const unsigned* ipack,
                                          int excl, unsigned& ov, unsigned& oi, int& ok)
{
    float nd[8]; unsigned ni[8]; int nk[8];
#pragma unroll
    for (int j = 0; j < 8; j++) {
        int a = 2 * j, b = a + 1;
        float da = (a == excl) ? 0.0f : dmin[a];
        float db = (b == excl) ? 0.0f : dmin[b];
        unsigned ia = ipack[j] & 0xFFFFu;
        unsigned ib = ipack[j] >> 16;
        bool c = (da > db) || (da == db && ia < ib);
        nd[j] = c ? da : db; ni[j] = c ? ia : ib; nk[j] = c ? a : b;
    }
#pragma unroll
    for (int lvl = 4; lvl >= 1; lvl >>= 1)
        for (int j = 0; j < lvl; j++) {
            int a = 2 * j, b = a + 1;
            bool c = (nd[a] > nd[b]) || (nd[a] == nd[b] && ni[a] < ni[b]);
            nd[j] = c ? nd[a] : nd[b]; ni[j] = c ? ni[a] : ni[b]; nk[j] = c ? nk[a] : nk[b];
        }
    ov = __float_as_uint(nd[0]); oi = ni[0]; ok = nk[0];
}

// ---------------- kernel 1: x1 / f1 ----------------
__global__ void __launch_bounds__(256) k_pre(
    const float* __restrict__ p, const float* __restrict__ x,
    const float* __restrict__ w0,
    const float* __restrict__ g0, const float* __restrict__ b0,
    const float* __restrict__ m0, const float* __restrict__ v0,
    const float* __restrict__ w1, const float* __restrict__ bias1,
    const float* __restrict__ g1, const float* __restrict__ b1_,
    const float* __restrict__ m1, const float* __restrict__ v1,
    float* __restrict__ out)
{
    __shared__ float x1s[8][32];
    int ch = threadIdx.x & 31;
    int lp = threadIdx.x >> 5;
    int pt = blockIdx.x * 8 + lp;

    float acc = 0.f;
#pragma unroll
    for (int i = 0; i < 6; i++)
        acc = fmaf(__ldg(&x[pt * 6 + i]), __ldg(&w0[i * 32 + ch]), acc);
    float s0 = __ldg(&g0[ch]) / sqrtf(__ldg(&v0[ch]) + 1e-5f);
    float val = (acc - __ldg(&m0[ch])) * s0 + __ldg(&b0[ch]);
    val = fmaxf(val, 0.f);
    x1s[lp][ch] = val;
    g_x1[pt * 32 + ch] = val;

    if (ch == 0) {
        float px = p[pt * 3], py = p[pt * 3 + 1], pz = p[pt * 3 + 2];
        g_pw[pt] = make_float4(px, py, pz, sq3_fma(px, py, pz));
    }
    __syncthreads();

    float a1 = __ldg(&bias1[ch]);
#pragma unroll
    for (int i = 0; i < 32; i++)
        a1 = fmaf(x1s[lp][i], __ldg(&w1[i * 32 + ch]), a1);
    float s1 = __ldg(&g1[ch]) / sqrtf(__ldg(&v1[ch]) + 1e-5f);
    float f1 = (a1 - __ldg(&m1[ch])) * s1 + __ldg(&b1_[ch]);
    out[pt * 32 + ch] = fmaxf(f1, 0.f);
}

// ---------------- kernel 2: merged sort prep (bbox + Morton count + scan) ----------------
__device__ __forceinline__ int spread3(int v) {   // 3-bit v -> bits 0,3,6
    return (v & 1) | ((v & 2) << 2) | ((v & 4) << 4);
}
__global__ void __launch_bounds__(1024) k_sortA()
{
    __shared__ float s[6][32];
    __shared__ float s_par[6];
    __shared__ int s_cnt[NCELL];
    __shared__ int s_scan[NCELL];
    int tid = threadIdx.x;
    int lane = tid & 31, wid = tid >> 5;

    float lx = 3.4e38f, ly = 3.4e38f, lz = 3.4e38f;
    float hx = -3.4e38f, hy = -3.4e38f, hz = -3.4e38f;
    for (int i = tid; i < NPTS; i += 1024) {
        float4 pw = g_pw[i];
        lx = fminf(lx, pw.x); ly = fminf(ly, pw.y); lz = fminf(lz, pw.z);
        hx = fmaxf(hx, pw.x); hy = fmaxf(hy, pw.y); hz = fmaxf(hz, pw.z);
    }
#pragma unroll
    for (int off = 16; off; off >>= 1) {
        lx = fminf(lx, __shfl_xor_sync(0xffffffffu, lx, off));
        ly = fminf(ly, __shfl_xor_sync(0xffffffffu, ly, off));
        lz = fminf(lz, __shfl_xor_sync(0xffffffffu, lz, off));
        hx = fmaxf(hx, __shfl_xor_sync(0xffffffffu, hx, off));
        hy = fmaxf(hy, __shfl_xor_sync(0xffffffffu, hy, off));
        hz = fmaxf(hz, __shfl_xor_sync(0xffffffffu, hz, off));
    }
    if (lane == 0) { s[0][wid] = lx; s[1][wid] = ly; s[2][wid] = lz;
                     s[3][wid] = hx; s[4][wid] = hy; s[5][wid] = hz; }
    if (tid < NCELL) s_cnt[tid] = 0;
    __syncthreads();
    if (tid == 0) {
        float v0 = s[0][0], v1 = s[1][0], v2 = s[2][0];
        float v3 = s[3][0], v4 = s[4][0], v5 = s[5][0];
        for (int k = 1; k < 32; k++) {
            v0 = fminf(v0, s[0][k]); v1 = fminf(v1, s[1][k]); v2 = fminf(v2, s[2][k]);
            v3 = fmaxf(v3, s[3][k]); v4 = fmaxf(v4, s[4][k]); v5 = fmaxf(v5, s[5][k]);
        }
        s_par[0] = v0; s_par[1] = v1; s_par[2] = v2;
        s_par[3] = 8.0f / fmaxf(v3 - v0, 1e-9f);
        s_par[4] = 8.0f / fmaxf(v4 - v1, 1e-9f);
        s_par[5] = 8.0f / fmaxf(v5 - v2, 1e-9f);
    }
    __syncthreads();
    float lox = s_par[0], loy = s_par[1], loz = s_par[2];
    float sx = s_par[3], sy = s_par[4], sz = s_par[5];
    for (int i = tid; i < NPTS; i += 1024) {
        float4 pw = g_pw[i];
        int cx = min(7, max(0, (int)((pw.x - lox) * sx)));
        int cy = min(7, max(0, (int)((pw.y - loy) * sy)));
        int cz = min(7, max(0, (int)((pw.z - loz) * sz)));
        int cell = spread3(cx) | (spread3(cy) << 1) | (spread3(cz) << 2);
        int rank = atomicAdd(&s_cnt[cell], 1);
        g_ptcell[i] = cell;
        g_rank[i] = rank;
    }
    __syncthreads();
    if (tid < NCELL) s_scan[tid] = s_cnt[tid];
    __syncthreads();
    for (int off = 1; off < NCELL; off <<= 1) {
        int v = (tid < NCELL && tid >= off) ? s_scan[tid - off] : 0;
        __syncthreads();
        if (tid < NCELL) s_scan[tid] += v;
        __syncthreads();
    }
    if (tid < NCELL) g_cellstart[tid + 1] = s_scan[tid];
    if (tid == 0) g_cellstart[0] = 0;
}

// ---------------- kernel 3: scatter ----------------
__global__ void __launch_bounds__(256) k_sortB()
{
    int i = blockIdx.x * 256 + threadIdx.x;
    float4 pw = g_pw[i];
    int pos = g_cellstart[g_ptcell[i]] + g_rank[i];
    g_sp[pos] = make_float4(pw.x, pw.y, pw.z, __uint_as_float((unsigned)i));
}

// ---------------- kernel 4: FPS, batched-2 selections per sync round ----------------
#define F_XY   0                          // float2[16384] 131072
#define F_Z    131072                     // float[16384]  65536
#define F_WK1  196608                     // u64[32]  256
#define F_WK2  (F_WK1 + 256)              // u64[32]  256
#define F_W1X  (F_WK2 + 256)              // f32[32] x6 planes
#define F_W1Y  (F_W1X + 128)
#define F_W1Z  (F_W1Y + 128)
#define F_W2X  (F_W1Z + 128)
#define F_W2Y  (F_W2X + 128)
#define F_W2Z  (F_W2Y + 128)
#define F_BQ   (F_W2Z + 128)              // float4[2]
#define FPS_SMEM (F_BQ + 32)

__global__ void __launch_bounds__(1024) k_fps12()
{
    extern __shared__ unsigned char sraw[];
    float2* s_xy = (float2*)(sraw + F_XY);
    float*  s_z  = (float*)(sraw + F_Z);
    unsigned long long* s_w1 = (unsigned long long*)(sraw + F_WK1);
    unsigned long long* s_w2 = (unsigned long long*)(sraw + F_WK2);
    float* s_w1x = (float*)(sraw + F_W1X);
    float* s_w1y = (float*)(sraw + F_W1Y);
    float* s_w1z = (float*)(sraw + F_W1Z);
    float* s_w2x = (float*)(sraw + F_W2X);
    float* s_w2y = (float*)(sraw + F_W2Y);
    float* s_w2z = (float*)(sraw + F_W2Z);
    float4* s_bq = (float4*)(sraw + F_BQ);

    const int tid = threadIdx.x;
    const int lane = tid & 31;
    const int w = tid >> 5;

    // load own 16 Morton-sorted points -> smem planes; build bbox + packed idx
    float dmin[16];
    unsigned ipack[8];
    float lox = 3.4e38f, loy = 3.4e38f, loz = 3.4e38f;
    float hix = -3.4e38f, hiy = -3.4e38f, hiz = -3.4e38f;
#pragma unroll
    for (int k = 0; k < 16; k++) {
        float4 sp = __ldg(&g_sp[tid * 16 + k]);
        s_xy[k * 1024 + tid] = make_float2(sp.x, sp.y);
        s_z[k * 1024 + tid] = sp.z;
        lox = fminf(lox, sp.x); hix = fmaxf(hix, sp.x);
        loy = fminf(loy, sp.y); hiy = fmaxf(hiy, sp.y);
        loz = fminf(loz, sp.z); hiz = fmaxf(hiz, sp.z);
        unsigned ib = __float_as_uint(sp.w);     // orig idx < 16384, fits 16 bits
        if (k & 1) ipack[k >> 1] |= (ib << 16); else ipack[k >> 1] = ib;
        dmin[k] = 1e10f;
    }
    // cached per-thread top-2 (sentinel +inf forces first-round rescan)
    unsigned t1v = 0x7F800000u, t1i = 0xFFFFFFFFu; int t1k = 0;
    unsigned t2v = 0x7F800000u, t2i = 0xFFFFFFFFu; int t2k = 0;
    if (tid == 0) g_idx[0] = 0;
    if (tid < 32) { s_w1[tid] = 0ull; s_w2[tid] = 0ull; }
    __syncthreads();

    float4 p0 = g_pw[0];
    float q1x = p0.x, q1y = p0.y, q1z = p0.z;
    float q2x = 0.f, q2y = 0.f, q2z = 0.f;
    int nsel = 1;
    int it = 1;

    while (it < MPTS) {
        // ---- worker phase: prune/update vs up to 2 new samples ----
        float cvalf = __uint_as_float(t1v);
        float dxl = fmaxf(0.f, fmaxf(lox - q1x, q1x - hix));
        float dyl = fmaxf(0.f, fmaxf(loy - q1y, q1y - hiy));
        float dzl = fmaxf(0.f, fmaxf(loz - q1z, q1z - hiz));
        float lb1 = dxl * dxl + dyl * dyl + dzl * dzl;
        bool act1 = !(lb1 * 0.9999f >= cvalf);
        bool act2 = false;
        if (nsel == 2) {
            float ex = fmaxf(0.f, fmaxf(lox - q2x, q2x - hix));
            float ey = fmaxf(0.f, fmaxf(loy - q2y, q2y - hiy));
            float ez = fmaxf(0.f, fmaxf(loz - q2z, q2z - hiz));
            float lb2 = ex * ex + ey * ey + ez * ez;
            act2 = !(lb2 * 0.9999f >= cvalf);
        }
        bool active = act1 || act2;

        if (__ballot_sync(0xffffffffu, active)) {
            if (active) {
#pragma unroll
                for (int k = 0; k < 16; k++) {
                    float2 xy = s_xy[k * 1024 + tid];
                    float pz = s_z[k * 1024 + tid];
                    if (act1) {
                        float dx = __fsub_rn(xy.x, q1x);
                        float dy = __fsub_rn(xy.y, q1y);
                        float dz = __fsub_rn(pz, q1z);
                        dmin[k] = fminf(dmin[k], sq3_fma(dx, dy, dz));
                    }
                    if (act2) {
                        float dx = __fsub_rn(xy.x, q2x);
                        float dy = __fsub_rn(xy.y, q2y);
                        float dz = __fsub_rn(pz, q2z);
                        dmin[k] = fminf(dmin[k], sq3_fma(dx, dy, dz));
                    }
                }
                tourney16(dmin, ipack, -1, t1v, t1i, t1k);
                tourney16(dmin, ipack, t1k, t2v, t2i, t2k);
            }
            // warp top-2 reduce over cached (t1, t2)
            unsigned r1v = redux_max_u32(t1v);
            unsigned r1i = redux_min_u32((t1v == r1v) ? t1i : 0xFFFFFFFFu);
            bool own1 = (t1v == r1v) && (t1i == r1i);
            unsigned cv = own1 ? t2v : t1v;
            unsigned ci = own1 ? t2i : t1i;
            int      ck = own1 ? t2k : t1k;
            unsigned r2v = redux_max_u32(cv);
            unsigned r2i = redux_min_u32((cv == r2v) ? ci : 0xFFFFFFFFu);
            bool own2 = (cv == r2v) && (ci == r2i);
            if (own1) {
                s_w1[w] = ((unsigned long long)r1v << 32) | (unsigned long long)(0xFFFFFFFFu - r1i);
                float2 xy = s_xy[t1k * 1024 + tid];
                s_w1x[w] = xy.x; s_w1y[w] = xy.y; s_w1z[w] = s_z[t1k * 1024 + tid];
            }
            if (own2) {
                s_w2[w] = ((unsigned long long)r2v << 32) | (unsigned long long)(0xFFFFFFFFu - r2i);
                float2 xy = s_xy[ck * 1024 + tid];
                s_w2x[w] = xy.x; s_w2y[w] = xy.y; s_w2z[w] = s_z[ck * 1024 + tid];
            }
            __threadfence_block();
        }

        if (w == 0) {
            NBAR_SYNC(1);                       // all workers published
            unsigned long long k1 = s_w1[lane], k2 = s_w2[lane];
            unsigned h1 = (unsigned)(k1 >> 32), l1 = (unsigned)(k1 & 0xFFFFFFFFull);
            unsigned h2 = (unsigned)(k2 >> 32), l2 = (unsigned)(k2 & 0xFFFFFFFFull);
            // block top-1
            unsigned vA = redux_max_u32(h1);
            unsigned lA = redux_max_u32((h1 == vA) ? l1 : 0u);
            bool isA = (h1 == vA) && (l1 == lA);
            // block second (exclude A's element)
            unsigned chv = isA ? h2 : h1;
            unsigned clv = isA ? l2 : l1;
            unsigned vB = redux_max_u32(chv);
            unsigned lB = redux_max_u32((chv == vB) ? clv : 0u);
            bool isB = (chv == vB) && (clv == lB);
            int jA = __ffs(__ballot_sync(0xffffffffu, isA)) - 1;
            int jB = __ffs(__ballot_sync(0xffffffffu, isB)) - 1;
            bool srcSecond = __shfl_sync(0xffffffffu, isA, jB);
            float Ax = s_w1x[jA], Ay = s_w1y[jA], Az = s_w1z[jA];
            float Bx = srcSecond ? s_w2x[jB] : s_w1x[jB];
            float By = srcSecond ? s_w2y[jB] : s_w1y[jB];
            float Bz = srcSecond ? s_w2z[jB] : s_w1z[jB];
            // acceptance: d(B,A)^2 >= V2 (same fma-chain), V2 > 0
            float ddx = __fsub_rn(Bx, Ax);
            float ddy = __fsub_rn(By, Ay);
            float ddz = __fsub_rn(Bz, Az);
            float dAB = sq3_fma(ddx, ddy, ddz);
            bool accept = (vB != 0u) && (dAB >= __uint_as_float(vB)) && (it + 1 < MPTS);
            nsel = accept ? 2 : 1;
            if (lane == 0) {
                g_idx[it] = (int)(0xFFFFFFFFu - lA);
                if (accept) g_idx[it + 1] = (int)(0xFFFFFFFFu - lB);
                s_bq[0] = make_float4(Ax, Ay, Az, __int_as_float(nsel));
                s_bq[1] = make_float4(Bx, By, Bz, 0.f);
            }
            __threadfence_block();
            NBAR_ARRIVE(2);
            q1x = Ax; q1y = Ay; q1z = Az;
            q2x = Bx; q2y = By; q2z = Bz;
            it += nsel;
        } else {
            NBAR_ARRIVE(1);
            NBAR_SYNC(2);
            float4 b0 = s_bq[0], b1 = s_bq[1];
            q1x = b0.x; q1y = b0.y; q1z = b0.z;
            nsel = __float_as_int(b0.w);
            q2x = b1.x; q2y = b1.y; q2z = b1.z;
            it += nsel;
        }
    }
    __syncthreads();
    for (int i = tid; i < MPTS; i += 1024)
        g_np[i] = g_pw[g_idx[i]];
}

// ---------------- kernel 5: top-16 KNN ----------------
__global__ void __launch_bounds__(256) k_knn()
{
    __shared__ float sd[256 * 17];
    __shared__ int   sii[256 * 17];
    int lane = threadIdx.x & 31;
    int part = threadIdx.x >> 5;
    int q = blockIdx.x * 32 + lane;
    float4 nq = __ldg(&g_np[q]);

    float bd[16]; int bi[16];
#pragma unroll
    for (int k = 0; k < 16; k++) { bd[k] = 3.4e38f; bi[k] = 0x7fffffff; }
    float wmax = 3.4e38f; int wpos = 0, widx = 0x7fffffff;

    int j0 = part * 2048;
    for (int j = j0; j < j0 + 2048; ++j) {
        float4 c = __ldg(&g_pw[j]);
        float dot = dot3_fma(nq.x, nq.y, nq.z, c.x, c.y, c.z);
        float d = sqdist_expand(nq.w, dot, c.w);
        if (d < wmax || (d == wmax && j < widx)) {
            bd[wpos] = d; bi[wpos] = j;
            wmax = -1.f; widx = -1;
#pragma unroll
            for (int k = 0; k < 16; k++)
                if (bd[k] > wmax || (bd[k] == wmax && bi[k] > widx)) {
                    wmax = bd[k]; widx = bi[k]; wpos = k;
                }
        }
    }
    int sb = threadIdx.x * 17;
#pragma unroll
    for (int k = 0; k < 16; k++) { sd[sb + k] = bd[k]; sii[sb + k] = bi[k]; }
    __syncthreads();

    if (part == 0) {
#pragma unroll 1
        for (int s = 0; s < 16; s++) {
            float md = 3.5e38f; int mi = 0x7fffffff; int mloc = 0;
            for (int src = 0; src < 8; src++) {
                int tb = (src * 32 + lane) * 17;
#pragma unroll
                for (int e = 0; e < 16; e++) {
                    float dd = sd[tb + e]; int ii = sii[tb + e];
                    if (dd < md || (dd == md && ii < mi)) { md = dd; mi = ii; mloc = tb + e; }
                }
            }
            g_knn[q * 16 + s] = mi;
            sd[mloc] = 3.6e38f;
        }
    }
}

// ---------------- kernel 6: grouped conv + maxpool ----------------
__global__ void __launch_bounds__(64) k_group(
    const float* __restrict__ p, const float* __restrict__ wd,
    const float* __restrict__ gd, const float* __restrict__ bd_,
    const float* __restrict__ md, const float* __restrict__ vd)
{
    __shared__ float fs[16 * 35];
    int q = blockIdx.x;
    int c = threadIdx.x;
    float4 nq = __ldg(&g_np[q]);

    for (int e = c; e < 16 * 35; e += 64) {
        int k = e / 35, i = e - 35 * k;
        int j = __ldg(&g_knn[q * 16 + k]);
        float v;
        if (i < 3) {
            float qq = (i == 0) ? nq.x : (i == 1) ? nq.y : nq.z;
            v = __ldg(&p[j * 3 + i]) - qq;
        } else {
            v = g_x1[j * 32 + (i - 3)];
        }
        fs[e] = v;
    }
    __syncthreads();

    float s  = __ldg(&gd[c]) / sqrtf(__ldg(&vd[c]) + 1e-5f);
    float mm = __ldg(&md[c]);
    float bb = __ldg(&bd_[c]);
    float mx = -3.4e38f;
#pragma unroll 1
    for (int k = 0; k < 16; k++) {
        float acc = 0.f;
#pragma unroll
        for (int i = 0; i < 35; i++)
            acc = fmaf(fs[k * 35 + i], __ldg(&wd[i * 64 + c]), acc);
        float h = fmaxf((acc - mm) * s + bb, 0.f);
        mx = fmaxf(mx, h);
    }
    g_x2[q * 64 + c] = mx;
}

// ---------------- kernel 7: f2 ----------------
__global__ void __launch_bounds__(256) k_f2(
    const float* __restrict__ w2, const float* __restrict__ b2,
    const float* __restrict__ g2, const float* __restrict__ bb2,
    const float* __restrict__ m2, const float* __restrict__ v2)
{
    int t = blockIdx.x * blockDim.x + threadIdx.x;
    int m = t >> 5, c = t & 31;
    float acc = __ldg(&b2[c]);
#pragma unroll 8
    for (int i = 0; i < 64; i++)
        acc = fmaf(g_x2[m * 64 + i], __ldg(&w2[i * 32 + c]), acc);
    float s = __ldg(&g2[c]) / sqrtf(__ldg(&v2[c]) + 1e-5f);
    float f = (acc - __ldg(&m2[c])) * s + __ldg(&bb2[c]);
    g_f2[t] = fmaxf(f, 0.f);
}

// ---------------- kernel 8: 3-NN interpolation ----------------
__global__ void __launch_bounds__(128) k_interp(float* __restrict__ out)
{
    int pt = blockIdx.x * 128 + threadIdx.x;
    float4 qp = g_pw[pt];

    float d0 = 3.4e38f, d1 = 3.4e38f, d2 = 3.4e38f;
    int   i0 = 0x7ffffffe, i1 = 0x7ffffffe, i2 = 0x7ffffffe;
    for (int j = 0; j < MPTS; ++j) {
        float4 c = __ldg(&g_np[j]);
        float dot = dot3_fma(qp.x, qp.y, qp.z, c.x, c.y, c.z);
        float d = sqdist_expand(qp.w, dot, c.w);
        if (d < d2 || (d == d2 && j < i2)) {
            if (d < d1 || (d == d1 && j < i1)) {
                d2 = d1; i2 = i1;
                if (d < d0 || (d == d0 && j < i0)) { d1 = d0; i1 = i0; d0 = d; i0 = j; }
                else { d1 = d; i1 = j; }
            } else { d2 = d; i2 = j; }
        }
    }
    float w0 = 1.f / (sqrtf(fmaxf(d0, 0.f)) + 1e-8f);
    float w1 = 1.f / (sqrtf(fmaxf(d1, 0.f)) + 1e-8f);
    float w2 = 1.f / (sqrtf(fmaxf(d2, 0.f)) + 1e-8f);
    float ws = w0 + w1 + w2;
    w0 /= ws; w1 /= ws; w2 /= ws;

#pragma unroll
    for (int c = 0; c < 32; c++) {
        float v = g_f2[i0 * 32 + c] * w0 + g_f2[i1 * 32 + c] * w1 + g_f2[i2 * 32 + c] * w2;
        out[pt * 32 + c] += v;
    }
}

// ---------------- launch ----------------
extern "C" void kernel_launch(void* const* d_in, const int* in_sizes, int n_in,
                              void* d_out, int out_size)
{
    const float* p    = (const float*)d_in[0];
    const float* x    = (const float*)d_in[1];
    const float* w0   = (const float*)d_in[2];
    const float* bn0g = (const float*)d_in[3];
    const float* bn0b = (const float*)d_in[4];
    const float* bn0m = (const float*)d_in[5];
    const float* bn0v = (const float*)d_in[6];
    const float* wd   = (const float*)d_in[7];
    const float* bndg = (const float*)d_in[8];
    const float* bndb = (const float*)d_in[9];
    const float* bndm = (const float*)d_in[10];
    const float* bndv = (const float*)d_in[11];
    const float* w1   = (const float*)d_in[12];
    const float* b1   = (const float*)d_in[13];
    const float* bn1g = (const float*)d_in[14];
    const float* bn1b = (const float*)d_in[15];
    const float* bn1m = (const float*)d_in[16];
    const float* bn1v = (const float*)d_in[17];
    const float* w2   = (const float*)d_in[18];
    const float* b2   = (const float*)d_in[19];
    const float* bn2g = (const float*)d_in[20];
    const float* bn2b = (const float*)d_in[21];
    const float* bn2m = (const float*)d_in[22];
    const float* bn2v = (const float*)d_in[23];
    float* out = (float*)d_out;

    cudaFuncSetAttribute(k_fps12, cudaFuncAttributeMaxDynamicSharedMemorySize, FPS_SMEM);

    k_pre<<<NPTS / 8, 256>>>(p, x, w0, bn0g, bn0b, bn0m, bn0v,
                             w1, b1, bn1g, bn1b, bn1m, bn1v, out);
    k_sortA<<<1, 1024>>>();
    k_sortB<<<NPTS / 256, 256>>>();
    k_fps12<<<1, 1024, FPS_SMEM>>>();           // launch #4 -> ncu capture slot
    k_knn<<<MPTS / 32, 256>>>();
    k_group<<<MPTS, 64>>>(p, wd, bndg, bndb, bndm, bndv);
    k_f2<<<MPTS * 32 / 256, 256>>>(w2, b2, bn2g, bn2b, bn2m, bn2v);
    k_interp<<<NPTS / 128, 128>>>(out);
}

// round 16
// speedup vs baseline: 1.1248x; 1.1248x over previous
#include <cuda_runtime.h>

#define NPTS 16384
#define MPTS 4096
#define KNN  16
#define NCELL 512          // 8x8x8 grid, Morton-ordered (locality sort only)

// ---------------- scratch (device globals; no allocation) ----------------
__device__ float  g_x1[NPTS * 32];
__device__ float4 g_pw[NPTS];       // x, y, z, |p|^2
__device__ int    g_idx[MPTS];
__device__ float4 g_np[MPTS];
__device__ int    g_knn[MPTS * KNN];
__device__ float  g_x2[MPTS * 64];
__device__ float  g_f2[MPTS * 32];
// sort scratch
__device__ float4 g_sp[NPTS];                 // sorted: x,y,z, orig idx bits
__device__ int    g_cellstart[NCELL + 1];
__device__ int    g_rank[NPTS];
__device__ int    g_ptcell[NPTS];

__device__ __forceinline__ unsigned redux_max_u32(unsigned v) {
    unsigned r;
    asm("redux.sync.max.u32 %0, %1, 0xffffffff;" : "=r"(r) : "r"(v));
    return r;
}
__device__ __forceinline__ unsigned redux_min_u32(unsigned v) {
    unsigned r;
    asm("redux.sync.min.u32 %0, %1, 0xffffffff;" : "=r"(r) : "r"(v));
    return r;
}
#define NBAR_SYNC(id)   asm volatile("bar.sync %0, 1024;" :: "r"(id) : "memory")
#define NBAR_ARRIVE(id) asm volatile("bar.arrive %0, 1024;" :: "r"(id) : "memory")

// XLA-matching primitives (DO NOT CHANGE: bit-exactness of selections)
__device__ __forceinline__ float sq3_fma(float x, float y, float z) {
    return __fmaf_rn(z, z, __fmaf_rn(y, y, __fmul_rn(x, x)));
}
__device__ __forceinline__ float dot3_fma(float ax, float ay, float az,
                                          float bx, float by, float bz) {
    return __fmaf_rn(az, bz, __fmaf_rn(ay, by, __fmul_rn(ax, bx)));
}
__device__ __forceinline__ float sqdist_expand(float aw, float dot, float bw) {
    return __fadd_rn(__fsub_rn(aw, __fmul_rn(2.0f, dot)), bw);
}

// ---------------- kernel 1: x1 / f1 ----------------
__global__ void __launch_bounds__(256) k_pre(
    const float* __restrict__ p, const float* __restrict__ x,
    const float* __restrict__ w0,
    const float* __restrict__ g0, const float* __restrict__ b0,
    const float* __restrict__ m0, const float* __restrict__ v0,
    const float* __restrict__ w1, const float* __restrict__ bias1,
    const float* __restrict__ g1, const float* __restrict__ b1_,
    const float* __restrict__ m1, const float* __restrict__ v1,
    float* __restrict__ out)
{
    __shared__ float x1s[8][32];
    int ch = threadIdx.x & 31;
    int lp = threadIdx.x >> 5;
    int pt = blockIdx.x * 8 + lp;

    float acc = 0.f;
#pragma unroll
    for (int i = 0; i < 6; i++)
        acc = fmaf(__ldg(&x[pt * 6 + i]), __ldg(&w0[i * 32 + ch]), acc);
    float s0 = __ldg(&g0[ch]) / sqrtf(__ldg(&v0[ch]) + 1e-5f);
    float val = (acc - __ldg(&m0[ch])) * s0 + __ldg(&b0[ch]);
    val = fmaxf(val, 0.f);
    x1s[lp][ch] = val;
    g_x1[pt * 32 + ch] = val;

    if (ch == 0) {
        float px = p[pt * 3], py = p[pt * 3 + 1], pz = p[pt * 3 + 2];
        g_pw[pt] = make_float4(px, py, pz, sq3_fma(px, py, pz));
    }
    __syncthreads();

    float a1 = __ldg(&bias1[ch]);
#pragma unroll
    for (int i = 0; i < 32; i++)
        a1 = fmaf(x1s[lp][i], __ldg(&w1[i * 32 + ch]), a1);
    float s1 = __ldg(&g1[ch]) / sqrtf(__ldg(&v1[ch]) + 1e-5f);
    float f1 = (a1 - __ldg(&m1[ch])) * s1 + __ldg(&b1_[ch]);
    out[pt * 32 + ch] = fmaxf(f1, 0.f);
}

// ---------------- kernel 2: merged sort prep (bbox + Morton count + scan) ----------------
__device__ __forceinline__ int spread3(int v) {   // 3-bit v -> bits 0,3,6
    return (v & 1) | ((v & 2) << 2) | ((v & 4) << 4);
}
__global__ void __launch_bounds__(1024) k_sortA()
{
    __shared__ float s[6][32];
    __shared__ float s_par[6];
    __shared__ int s_cnt[NCELL];
    __shared__ int s_scan[NCELL];
    int tid = threadIdx.x;
    int lane = tid & 31, wid = tid >> 5;

    float lx = 3.4e38f, ly = 3.4e38f, lz = 3.4e38f;
    float hx = -3.4e38f, hy = -3.4e38f, hz = -3.4e38f;
    for (int i = tid; i < NPTS; i += 1024) {
        float4 pw = g_pw[i];
        lx = fminf(lx, pw.x); ly = fminf(ly, pw.y); lz = fminf(lz, pw.z);
        hx = fmaxf(hx, pw.x); hy = fmaxf(hy, pw.y); hz = fmaxf(hz, pw.z);
    }
#pragma unroll
    for (int off = 16; off; off >>= 1) {
        lx = fminf(lx, __shfl_xor_sync(0xffffffffu, lx, off));
        ly = fminf(ly, __shfl_xor_sync(0xffffffffu, ly, off));
        lz = fminf(lz, __shfl_xor_sync(0xffffffffu, lz, off));
        hx = fmaxf(hx, __shfl_xor_sync(0xffffffffu, hx, off));
        hy = fmaxf(hy, __shfl_xor_sync(0xffffffffu, hy, off));
        hz = fmaxf(hz, __shfl_xor_sync(0xffffffffu, hz, off));
    }
    if (lane == 0) { s[0][wid] = lx; s[1][wid] = ly; s[2][wid] = lz;
                     s[3][wid] = hx; s[4][wid] = hy; s[5][wid] = hz; }
    if (tid < NCELL) s_cnt[tid] = 0;
    __syncthreads();
    if (tid == 0) {
        float v0 = s[0][0], v1 = s[1][0], v2 = s[2][0];
        float v3 = s[3][0], v4 = s[4][0], v5 = s[5][0];
        for (int k = 1; k < 32; k++) {
            v0 = fminf(v0, s[0][k]); v1 = fminf(v1, s[1][k]); v2 = fminf(v2, s[2][k]);
            v3 = fmaxf(v3, s[3][k]); v4 = fmaxf(v4, s[4][k]); v5 = fmaxf(v5, s[5][k]);
        }
        s_par[0] = v0; s_par[1] = v1; s_par[2] = v2;
        s_par[3] = 8.0f / fmaxf(v3 - v0, 1e-9f);
        s_par[4] = 8.0f / fmaxf(v4 - v1, 1e-9f);
        s_par[5] = 8.0f / fmaxf(v5 - v2, 1e-9f);
    }
    __syncthreads();
    float lox = s_par[0], loy = s_par[1], loz = s_par[2];
    float sx = s_par[3], sy = s_par[4], sz = s_par[5];
    for (int i = tid; i < NPTS; i += 1024) {
        float4 pw = g_pw[i];
        int cx = min(7, max(0, (int)((pw.x - lox) * sx)));
        int cy = min(7, max(0, (int)((pw.y - loy) * sy)));
        int cz = min(7, max(0, (int)((pw.z - loz) * sz)));
        int cell = spread3(cx) | (spread3(cy) << 1) | (spread3(cz) << 2);
        int rank = atomicAdd(&s_cnt[cell], 1);
        g_ptcell[i] = cell;
        g_rank[i] = rank;
    }
    __syncthreads();
    if (tid < NCELL) s_scan[tid] = s_cnt[tid];
    __syncthreads();
    for (int off = 1; off < NCELL; off <<= 1) {
        int v = (tid < NCELL && tid >= off) ? s_scan[tid - off] : 0;
        __syncthreads();
        if (tid < NCELL) s_scan[tid] += v;
        __syncthreads();
    }
    if (tid < NCELL) g_cellstart[tid + 1] = s_scan[tid];
    if (tid == 0) g_cellstart[0] = 0;
}

// ---------------- kernel 3: scatter ----------------
__global__ void __launch_bounds__(256) k_sortB()
{
    int i = blockIdx.x * 256 + threadIdx.x;
    float4 pw = g_pw[i];
    int pos = g_cellstart[g_ptcell[i]] + g_rank[i];
    g_sp[pos] = make_float4(pw.x, pw.y, pw.z, __uint_as_float((unsigned)i));
}

// ---------------- kernel 4: FPS, producer/consumer named barriers, no fences ----------------
#define F_XY   0                          // float2[16384] 131072
#define F_Z    131072                     // float[16384]  65536
#define F_WK   196608                     // u64[32]  256
#define F_WX   (F_WK + 256)               // f32[32]
#define F_WY   (F_WX + 128)
#define F_WZ   (F_WY + 128)
#define F_BQ   (F_WZ + 128)               // float4
#define FPS_SMEM (F_BQ + 16)

__global__ void __launch_bounds__(1024) k_fps13()
{
    extern __shared__ unsigned char sraw[];
    float2* s_xy = (float2*)(sraw + F_XY);
    float*  s_z  = (float*)(sraw + F_Z);
    unsigned long long* s_wk = (unsigned long long*)(sraw + F_WK);
    float* s_wx = (float*)(sraw + F_WX);
    float* s_wy = (float*)(sraw + F_WY);
    float* s_wz = (float*)(sraw + F_WZ);
    float4* s_bq = (float4*)(sraw + F_BQ);

    const int tid = threadIdx.x;
    const int lane = tid & 31;
    const int w = tid >> 5;

    // load own 16 Morton-sorted points -> smem planes; build bbox + packed idx
    float dmin[16];
    unsigned ipack[8];
    float lox = 3.4e38f, loy = 3.4e38f, loz = 3.4e38f;
    float hix = -3.4e38f, hiy = -3.4e38f, hiz = -3.4e38f;
#pragma unroll
    for (int k = 0; k < 16; k++) {
        float4 sp = __ldg(&g_sp[tid * 16 + k]);
        s_xy[k * 1024 + tid] = make_float2(sp.x, sp.y);
        s_z[k * 1024 + tid] = sp.z;
        lox = fminf(lox, sp.x); hix = fmaxf(hix, sp.x);
        loy = fminf(loy, sp.y); hiy = fmaxf(hiy, sp.y);
        loz = fminf(loz, sp.z); hiz = fmaxf(hiz, sp.z);
        unsigned ib = __float_as_uint(sp.w);     // orig idx < 16384, fits 16 bits
        if (k & 1) ipack[k >> 1] |= (ib << 16); else ipack[k >> 1] = ib;
        dmin[k] = 1e10f;
    }
    unsigned cval = 0x7F800000u;   // +inf -> force active at it=1
    unsigned cidx = 0xFFFFFFFFu;
    int ckp = 0;
    if (tid == 0) g_idx[0] = 0;
    __syncthreads();

    float qx = g_pw[0].x, qy = g_pw[0].y, qz = g_pw[0].z;

    for (int it = 1; it < MPTS; ++it) {
        // ---- worker part (all warps, q already in registers) ----
        float dxl = fmaxf(0.f, fmaxf(lox - qx, qx - hix));
        float dyl = fmaxf(0.f, fmaxf(loy - qy, qy - hiy));
        float dzl = fmaxf(0.f, fmaxf(loz - qz, qz - hiz));
        float lb = dxl * dxl + dyl * dyl + dzl * dzl;
        bool active = !(lb * 0.9999f >= __uint_as_float(cval));

        if (__ballot_sync(0xffffffffu, active)) {
            if (active) {
#pragma unroll
                for (int k = 0; k < 16; k++) {
                    float2 xy = s_xy[k * 1024 + tid];
                    float pz = s_z[k * 1024 + tid];
                    float dx = __fsub_rn(xy.x, qx);
                    float dy = __fsub_rn(xy.y, qy);
                    float dz = __fsub_rn(pz, qz);
                    float d = sq3_fma(dx, dy, dz);
                    dmin[k] = fminf(dmin[k], d);
                }
                // 4-level tournament, lex (max d, min orig idx) == sequential chain
                float nd[8]; unsigned ni[8]; int nk[8];
#pragma unroll
                for (int j = 0; j < 8; j++) {
                    int a = 2 * j, b = a + 1;
                    unsigned ia = (ipack[j] >> 0) & 0xFFFFu;
                    unsigned ib = (ipack[j] >> 16) & 0xFFFFu;
                    bool c = (dmin[a] > dmin[b]) || (dmin[a] == dmin[b] && ia < ib);
                    nd[j] = c ? dmin[a] : dmin[b];
                    ni[j] = c ? ia : ib;
                    nk[j] = c ? a : b;
                }
#pragma unroll
                for (int lvl = 4; lvl >= 1; lvl >>= 1) {
                    for (int j = 0; j < lvl; j++) {
                        int a = 2 * j, b = a + 1;
                        bool c = (nd[a] > nd[b]) || (nd[a] == nd[b] && ni[a] < ni[b]);
                        nd[j] = c ? nd[a] : nd[b];
                        ni[j] = c ? ni[a] : ni[b];
                        nk[j] = c ? nk[a] : nk[b];
                    }
                }
                cval = __float_as_uint(nd[0]);
                cidx = ni[0];
                ckp = nk[0];
            }
            unsigned vmax = redux_max_u32(cval);
            unsigned imin = redux_min_u32((cval == vmax) ? cidx : 0xFFFFFFFFu);
            if (cval == vmax && cidx == imin) {   // unique winner lane
                float2 xy = s_xy[ckp * 1024 + tid];
                float zz = s_z[ckp * 1024 + tid];
                s_wk[w] = ((unsigned long long)vmax << 32) | (unsigned long long)(0xFFFFFFFFu - imin);
                s_wx[w] = xy.x; s_wy[w] = xy.y; s_wz[w] = zz;
            }
        }

        if (w == 0) {
            NBAR_SYNC(1);                       // wait: all workers published (drains STS)
            unsigned long long k64 = s_wk[lane];
            unsigned hi = (unsigned)(k64 >> 32);
            unsigned lo = (unsigned)(k64 & 0xFFFFFFFFull);
            unsigned vmax = redux_max_u32(hi);
            unsigned lomax = redux_max_u32((hi == vmax) ? lo : 0u);
            bool win = (hi == vmax && lo == lomax);
            unsigned bal = __ballot_sync(0xffffffffu, win);
            int jstar = __ffs(bal) - 1;
            if (win) g_idx[it] = (int)(0xFFFFFFFFu - lomax);
            float nqx = s_wx[jstar], nqy = s_wy[jstar], nqz = s_wz[jstar];
            if (lane == 0) s_bq[0] = make_float4(nqx, nqy, nqz, 0.f);
            NBAR_ARRIVE(2);                     // release workers
            qx = nqx; qy = nqy; qz = nqz;       // keep q in registers, overlap next part
        } else {
            NBAR_ARRIVE(1);                     // non-blocking
            NBAR_SYNC(2);                       // wait: q published (drains warp0's STS)
            float4 qv = s_bq[0];
            qx = qv.x; qy = qv.y; qz = qv.z;
        }
    }
    __syncthreads();
    for (int i = tid; i < MPTS; i += 1024)
        g_np[i] = g_pw[g_idx[i]];
}

// ---------------- kernel 5: top-16 KNN ----------------
__global__ void __launch_bounds__(256) k_knn()
{
    __shared__ float sd[256 * 17];
    __shared__ int   sii[256 * 17];
    int lane = threadIdx.x & 31;
    int part = threadIdx.x >> 5;
    int q = blockIdx.x * 32 + lane;
    float4 nq = __ldg(&g_np[q]);

    float bd[16]; int bi[16];
#pragma unroll
    for (int k = 0; k < 16; k++) { bd[k] = 3.4e38f; bi[k] = 0x7fffffff; }
    float wmax = 3.4e38f; int wpos = 0, widx = 0x7fffffff;

    int j0 = part * 2048;
    for (int j = j0; j < j0 + 2048; ++j) {
        float4 c = __ldg(&g_pw[j]);
        float dot = dot3_fma(nq.x, nq.y, nq.z, c.x, c.y, c.z);
        float d = sqdist_expand(nq.w, dot, c.w);
        if (d < wmax || (d == wmax && j < widx)) {
            bd[wpos] = d; bi[wpos] = j;
            wmax = -1.f; widx = -1;
#pragma unroll
            for (int k = 0; k < 16; k++)
                if (bd[k] > wmax || (bd[k] == wmax && bi[k] > widx)) {
                    wmax = bd[k]; widx = bi[k]; wpos = k;
                }
        }
    }
    int sb = threadIdx.x * 17;
#pragma unroll
    for (int k = 0; k < 16; k++) { sd[sb + k] = bd[k]; sii[sb + k] = bi[k]; }
    __syncthreads();

    if (part == 0) {
#pragma unroll 1
        for (int s = 0; s < 16; s++) {
            float md = 3.5e38f; int mi = 0x7fffffff; int mloc = 0;
            for (int src = 0; src < 8; src++) {
                int tb = (src * 32 + lane) * 17;
#pragma unroll
                for (int e = 0; e < 16; e++) {
                    float dd = sd[tb + e]; int ii = sii[tb + e];
                    if (dd < md || (dd == md && ii < mi)) { md = dd; mi = ii; mloc = tb + e; }
                }
            }
            g_knn[q * 16 + s] = mi;
            sd[mloc] = 3.6e38f;
        }
    }
}

// ---------------- kernel 6: grouped conv + maxpool ----------------
__global__ void __launch_bounds__(64) k_group(
    const float* __restrict__ p, const float* __restrict__ wd,
    const float* __restrict__ gd, const float* __restrict__ bd_,
    const float* __restrict__ md, const float* __restrict__ vd)
{
    __shared__ float fs[16 * 35];
    int q = blockIdx.x;
    int c = threadIdx.x;
    float4 nq = __ldg(&g_np[q]);

    for (int e = c; e < 16 * 35; e += 64) {
        int k = e / 35, i = e - 35 * k;
        int j = __ldg(&g_knn[q * 16 + k]);
        float v;
        if (i < 3) {
            float qq = (i == 0) ? nq.x : (i == 1) ? nq.y : nq.z;
            v = __ldg(&p[j * 3 + i]) - qq;
        } else {
            v = g_x1[j * 32 + (i - 3)];
        }
        fs[e] = v;
    }
    __syncthreads();

    float s  = __ldg(&gd[c]) / sqrtf(__ldg(&vd[c]) + 1e-5f);
    float mm = __ldg(&md[c]);
    float bb = __ldg(&bd_[c]);
    float mx = -3.4e38f;
#pragma unroll 1
    for (int k = 0; k < 16; k++) {
        float acc = 0.f;
#pragma unroll
        for (int i = 0; i < 35; i++)
            acc = fmaf(fs[k * 35 + i], __ldg(&wd[i * 64 + c]), acc);
        float h = fmaxf((acc - mm) * s + bb, 0.f);
        mx = fmaxf(mx, h);
    }
    g_x2[q * 64 + c] = mx;
}

// ---------------- kernel 7: f2 ----------------
__global__ void __launch_bounds__(256) k_f2(
    const float* __restrict__ w2, const float* __restrict__ b2,
    const float* __restrict__ g2, const float* __restrict__ bb2,
    const float* __restrict__ m2, const float* __restrict__ v2)
{
    int t = blockIdx.x * blockDim.x + threadIdx.x;
    int m = t >> 5, c = t & 31;
    float acc = __ldg(&b2[c]);
#pragma unroll 8
    for (int i = 0; i < 64; i++)
        acc = fmaf(g_x2[m * 64 + i], __ldg(&w2[i * 32 + c]), acc);
    float s = __ldg(&g2[c]) / sqrtf(__ldg(&v2[c]) + 1e-5f);
    float f = (acc - __ldg(&m2[c])) * s + __ldg(&bb2[c]);
    g_f2[t] = fmaxf(f, 0.f);
}

// ---------------- kernel 8: 3-NN interpolation ----------------
__global__ void __launch_bounds__(128) k_interp(float* __restrict__ out)
{
    int pt = blockIdx.x * 128 + threadIdx.x;
    float4 qp = g_pw[pt];

    float d0 = 3.4e38f, d1 = 3.4e38f, d2 = 3.4e38f;
    int   i0 = 0x7ffffffe, i1 = 0x7ffffffe, i2 = 0x7ffffffe;
    for (int j = 0; j < MPTS; ++j) {
        float4 c = __ldg(&g_np[j]);
        float dot = dot3_fma(qp.x, qp.y, qp.z, c.x, c.y, c.z);
        float d = sqdist_expand(qp.w, dot, c.w);
        if (d < d2 || (d == d2 && j < i2)) {
            if (d < d1 || (d == d1 && j < i1)) {
                d2 = d1; i2 = i1;
                if (d < d0 || (d == d0 && j < i0)) { d1 = d0; i1 = i0; d0 = d; i0 = j; }
                else { d1 = d; i1 = j; }
            } else { d2 = d; i2 = j; }
        }
    }
    float w0 = 1.f / (sqrtf(fmaxf(d0, 0.f)) + 1e-8f);
    float w1 = 1.f / (sqrtf(fmaxf(d1, 0.f)) + 1e-8f);
    float w2 = 1.f / (sqrtf(fmaxf(d2, 0.f)) + 1e-8f);
    float ws = w0 + w1 + w2;
    w0 /= ws; w1 /= ws; w2 /= ws;

#pragma unroll
    for (int c = 0; c < 32; c++) {
        float v = g_f2[i0 * 32 + c] * w0 + g_f2[i1 * 32 + c] * w1 + g_f2[i2 * 32 + c] * w2;
        out[pt * 32 + c] += v;
    }
}

// ---------------- launch ----------------
extern "C" void kernel_launch(void* const* d_in, const int* in_sizes, int n_in,
                              void* d_out, int out_size)
{
    const float* p    = (const float*)d_in[0];
    const float* x    = (const float*)d_in[1];
    const float* w0   = (const float*)d_in[2];
    const float* bn0g = (const float*)d_in[3];
    const float* bn0b = (const float*)d_in[4];
    const float* bn0m = (const float*)d_in[5];
    const float* bn0v = (const float*)d_in[6];
    const float* wd   = (const float*)d_in[7];
    const float* bndg = (const float*)d_in[8];
    const float* bndb = (const float*)d_in[9];
    const float* bndm = (const float*)d_in[10];
    const float* bndv = (const float*)d_in[11];
    const float* w1   = (const float*)d_in[12];
    const float* b1   = (const float*)d_in[13];
    const float* bn1g = (const float*)d_in[14];
    const float* bn1b = (const float*)d_in[15];
    const float* bn1m = (const float*)d_in[16];
    const float* bn1v = (const float*)d_in[17];
    const float* w2   = (const float*)d_in[18];
    const float* b2   = (const float*)d_in[19];
    const float* bn2g = (const float*)d_in[20];
    const float* bn2b = (const float*)d_in[21];
    const float* bn2m = (const float*)d_in[22];
    const float* bn2v = (const float*)d_in[23];
    float* out = (float*)d_out;

    cudaFuncSetAttribute(k_fps13, cudaFuncAttributeMaxDynamicSharedMemorySize, FPS_SMEM);

    k_pre<<<NPTS / 8, 256>>>(p, x, w0, bn0g, bn0b, bn0m, bn0v,
                             w1, b1, bn1g, bn1b, bn1m, bn1v, out);
    k_sortA<<<1, 1024>>>();
    k_sortB<<<NPTS / 256, 256>>>();
    k_fps13<<<1, 1024, FPS_SMEM>>>();           // launch #4 -> ncu capture slot
    k_knn<<<MPTS / 32, 256>>>();
    k_group<<<MPTS, 64>>>(p, wd, bndg, bndb, bndm, bndv);
    k_f2<<<MPTS * 32 / 256, 256>>>(w2, b2, bn2g, bn2b, bn2m, bn2v);
    k_interp<<<NPTS / 128, 128>>>(out);
}

// round 17
// speedup vs baseline: 1.1257x; 1.0008x over previous
#include <cuda_runtime.h>

#define NPTS 16384
#define MPTS 4096
#define KNN  16
#define NCELL 512          // 8x8x8 grid, Morton-ordered (locality sort only)

// ---------------- scratch (device globals; no allocation) ----------------
__device__ float  g_x1[NPTS * 32];
__device__ float4 g_pw[NPTS];       // x, y, z, |p|^2
__device__ int    g_idx[MPTS];
__device__ float4 g_np[MPTS];
__device__ int    g_knn[MPTS * KNN];
__device__ float  g_x2[MPTS * 64];
__device__ float  g_f2[MPTS * 32];
// sort scratch
__device__ float4 g_sp[NPTS];                 // sorted: x,y,z, orig idx bits
__device__ int    g_cellstart[NCELL + 1];
__device__ int    g_rank[NPTS];
__device__ int    g_ptcell[NPTS];

__device__ __forceinline__ unsigned redux_max_u32(unsigned v) {
    unsigned r;
    asm("redux.sync.max.u32 %0, %1, 0xffffffff;" : "=r"(r) : "r"(v));
    return r;
}
__device__ __forceinline__ unsigned redux_min_u32(unsigned v) {
    unsigned r;
    asm("redux.sync.min.u32 %0, %1, 0xffffffff;" : "=r"(r) : "r"(v));
    return r;
}
#define NBAR_SYNC(id)   asm volatile("bar.sync %0, 1024;" :: "r"(id) : "memory")
#define NBAR_ARRIVE(id) asm volatile("bar.arrive %0, 1024;" :: "r"(id) : "memory")

// XLA-matching primitives (DO NOT CHANGE: bit-exactness of selections)
__device__ __forceinline__ float sq3_fma(float x, float y, float z) {
    return __fmaf_rn(z, z, __fmaf_rn(y, y, __fmul_rn(x, x)));
}
__device__ __forceinline__ float dot3_fma(float ax, float ay, float az,
                                          float bx, float by, float bz) {
    return __fmaf_rn(az, bz, __fmaf_rn(ay, by, __fmul_rn(ax, bx)));
}
__device__ __forceinline__ float sqdist_expand(float aw, float dot, float bw) {
    return __fadd_rn(__fsub_rn(aw, __fmul_rn(2.0f, dot)), bw);
}

// ---------------- kernel 1: x1 / f1 ----------------
__global__ void __launch_bounds__(256) k_pre(
    const float* __restrict__ p, const float* __restrict__ x,
    const float* __restrict__ w0,
    const float* __restrict__ g0, const float* __restrict__ b0,
    const float* __restrict__ m0, const float* __restrict__ v0,
    const float* __restrict__ w1, const float* __restrict__ bias1,
    const float* __restrict__ g1, const float* __restrict__ b1_,
    const float* __restrict__ m1, const float* __restrict__ v1,
    float* __restrict__ out)
{
    __shared__ float x1s[8][32];
    int ch = threadIdx.x & 31;
    int lp = threadIdx.x >> 5;
    int pt = blockIdx.x * 8 + lp;

    float acc = 0.f;
#pragma unroll
    for (int i = 0; i < 6; i++)
        acc = fmaf(__ldg(&x[pt * 6 + i]), __ldg(&w0[i * 32 + ch]), acc);
    float s0 = __ldg(&g0[ch]) / sqrtf(__ldg(&v0[ch]) + 1e-5f);
    float val = (acc - __ldg(&m0[ch])) * s0 + __ldg(&b0[ch]);
    val = fmaxf(val, 0.f);
    x1s[lp][ch] = val;
    g_x1[pt * 32 + ch] = val;

    if (ch == 0) {
        float px = p[pt * 3], py = p[pt * 3 + 1], pz = p[pt * 3 + 2];
        g_pw[pt] = make_float4(px, py, pz, sq3_fma(px, py, pz));
    }
    __syncthreads();

    float a1 = __ldg(&bias1[ch]);
#pragma unroll
    for (int i = 0; i < 32; i++)
        a1 = fmaf(x1s[lp][i], __ldg(&w1[i * 32 + ch]), a1);
    float s1 = __ldg(&g1[ch]) / sqrtf(__ldg(&v1[ch]) + 1e-5f);
    float f1 = (a1 - __ldg(&m1[ch])) * s1 + __ldg(&b1_[ch]);
    out[pt * 32 + ch] = fmaxf(f1, 0.f);
}

// ---------------- kernel 2: merged sort prep (bbox + Morton count + scan) ----------------
__device__ __forceinline__ int spread3(int v) {   // 3-bit v -> bits 0,3,6
    return (v & 1) | ((v & 2) << 2) | ((v & 4) << 4);
}
__global__ void __launch_bounds__(1024) k_sortA()
{
    __shared__ float s[6][32];
    __shared__ float s_par[6];
    __shared__ int s_cnt[NCELL];
    __shared__ int s_scan[NCELL];
    int tid = threadIdx.x;
    int lane = tid & 31, wid = tid >> 5;

    float lx = 3.4e38f, ly = 3.4e38f, lz = 3.4e38f;
    float hx = -3.4e38f, hy = -3.4e38f, hz = -3.4e38f;
    for (int i = tid; i < NPTS; i += 1024) {
        float4 pw = g_pw[i];
        lx = fminf(lx, pw.x); ly = fminf(ly, pw.y); lz = fminf(lz, pw.z);
        hx = fmaxf(hx, pw.x); hy = fmaxf(hy, pw.y); hz = fmaxf(hz, pw.z);
    }
#pragma unroll
    for (int off = 16; off; off >>= 1) {
        lx = fminf(lx, __shfl_xor_sync(0xffffffffu, lx, off));
        ly = fminf(ly, __shfl_xor_sync(0xffffffffu, ly, off));
        lz = fminf(lz, __shfl_xor_sync(0xffffffffu, lz, off));
        hx = fmaxf(hx, __shfl_xor_sync(0xffffffffu, hx, off));
        hy = fmaxf(hy, __shfl_xor_sync(0xffffffffu, hy, off));
        hz = fmaxf(hz, __shfl_xor_sync(0xffffffffu, hz, off));
    }
    if (lane == 0) { s[0][wid] = lx; s[1][wid] = ly; s[2][wid] = lz;
                     s[3][wid] = hx; s[4][wid] = hy; s[5][wid] = hz; }
    if (tid < NCELL) s_cnt[tid] = 0;
    __syncthreads();
    if (tid == 0) {
        float v0 = s[0][0], v1 = s[1][0], v2 = s[2][0];
        float v3 = s[3][0], v4 = s[4][0], v5 = s[5][0];
        for (int k = 1; k < 32; k++) {
            v0 = fminf(v0, s[0][k]); v1 = fminf(v1, s[1][k]); v2 = fminf(v2, s[2][k]);
            v3 = fmaxf(v3, s[3][k]); v4 = fmaxf(v4, s[4][k]); v5 = fmaxf(v5, s[5][k]);
        }
        s_par[0] = v0; s_par[1] = v1; s_par[2] = v2;
        s_par[3] = 8.0f / fmaxf(v3 - v0, 1e-9f);
        s_par[4] = 8.0f / fmaxf(v4 - v1, 1e-9f);
        s_par[5] = 8.0f / fmaxf(v5 - v2, 1e-9f);
    }
    __syncthreads();
    float lox = s_par[0], loy = s_par[1], loz = s_par[2];
    float sx = s_par[3], sy = s_par[4], sz = s_par[5];
    for (int i = tid; i < NPTS; i += 1024) {
        float4 pw = g_pw[i];
        int cx = min(7, max(0, (int)((pw.x - lox) * sx)));
        int cy = min(7, max(0, (int)((pw.y - loy) * sy)));
        int cz = min(7, max(0, (int)((pw.z - loz) * sz)));
        int cell = spread3(cx) | (spread3(cy) << 1) | (spread3(cz) << 2);
        int rank = atomicAdd(&s_cnt[cell], 1);
        g_ptcell[i] = cell;
        g_rank[i] = rank;
    }
    __syncthreads();
    if (tid < NCELL) s_scan[tid] = s_cnt[tid];
    __syncthreads();
    for (int off = 1; off < NCELL; off <<= 1) {
        int v = (tid < NCELL && tid >= off) ? s_scan[tid - off] : 0;
        __syncthreads();
        if (tid < NCELL) s_scan[tid] += v;
        __syncthreads();
    }
    if (tid < NCELL) g_cellstart[tid + 1] = s_scan[tid];
    if (tid == 0) g_cellstart[0] = 0;
}

// ---------------- kernel 3: scatter ----------------
__global__ void __launch_bounds__(256) k_sortB()
{
    int i = blockIdx.x * 256 + threadIdx.x;
    float4 pw = g_pw[i];
    int pos = g_cellstart[g_ptcell[i]] + g_rank[i];
    g_sp[pos] = make_float4(pw.x, pw.y, pw.z, __uint_as_float((unsigned)i));
}

// ---------------- kernel 4: FPS, packed partials + SHFL coord extraction ----------------
#define F_XY   0                          // float2[16384] 131072
#define F_Z    131072                     // float[16384]  65536
#define F_WP   196608                     // float4[32]  512  {key_hi, key_lo, x, y}
#define F_WZ   (F_WP + 512)               // f32[32]
#define F_BQ   (F_WZ + 128)               // float4
#define FPS_SMEM (F_BQ + 16)

__global__ void __launch_bounds__(1024) k_fps14()
{
    extern __shared__ unsigned char sraw[];
    float2* s_xy = (float2*)(sraw + F_XY);
    float*  s_z  = (float*)(sraw + F_Z);
    float4* s_wp = (float4*)(sraw + F_WP);
    float*  s_wz = (float*)(sraw + F_WZ);
    float4* s_bq = (float4*)(sraw + F_BQ);

    const int tid = threadIdx.x;
    const int lane = tid & 31;
    const int w = tid >> 5;

    // load own 16 Morton-sorted points -> smem planes; build bbox + packed idx
    float dmin[16];
    unsigned ipack[8];
    float lox = 3.4e38f, loy = 3.4e38f, loz = 3.4e38f;
    float hix = -3.4e38f, hiy = -3.4e38f, hiz = -3.4e38f;
#pragma unroll
    for (int k = 0; k < 16; k++) {
        float4 sp = __ldg(&g_sp[tid * 16 + k]);
        s_xy[k * 1024 + tid] = make_float2(sp.x, sp.y);
        s_z[k * 1024 + tid] = sp.z;
        lox = fminf(lox, sp.x); hix = fmaxf(hix, sp.x);
        loy = fminf(loy, sp.y); hiy = fmaxf(hiy, sp.y);
        loz = fminf(loz, sp.z); hiz = fmaxf(hiz, sp.z);
        unsigned ib = __float_as_uint(sp.w);     // orig idx < 16384, fits 16 bits
        if (k & 1) ipack[k >> 1] |= (ib << 16); else ipack[k >> 1] = ib;
        dmin[k] = 1e10f;
    }
    unsigned cval = 0x7F800000u;   // +inf -> force active at it=1
    unsigned cidx = 0xFFFFFFFFu;
    int ckp = 0;
    if (tid == 0) g_idx[0] = 0;
    __syncthreads();

    float qx = g_pw[0].x, qy = g_pw[0].y, qz = g_pw[0].z;

    for (int it = 1; it < MPTS; ++it) {
        // ---- worker part (all warps, q already in registers) ----
        float dxl = fmaxf(0.f, fmaxf(lox - qx, qx - hix));
        float dyl = fmaxf(0.f, fmaxf(loy - qy, qy - hiy));
        float dzl = fmaxf(0.f, fmaxf(loz - qz, qz - hiz));
        float lb = dxl * dxl + dyl * dyl + dzl * dzl;
        bool active = !(lb * 0.9999f >= __uint_as_float(cval));

        if (__ballot_sync(0xffffffffu, active)) {
            if (active) {
#pragma unroll
                for (int k = 0; k < 16; k++) {
                    float2 xy = s_xy[k * 1024 + tid];
                    float pz = s_z[k * 1024 + tid];
                    float dx = __fsub_rn(xy.x, qx);
                    float dy = __fsub_rn(xy.y, qy);
                    float dz = __fsub_rn(pz, qz);
                    float d = sq3_fma(dx, dy, dz);
                    dmin[k] = fminf(dmin[k], d);
                }
                // 4-level tournament, lex (max d, min orig idx) == sequential chain
                float nd[8]; unsigned ni[8]; int nk[8];
#pragma unroll
                for (int j = 0; j < 8; j++) {
                    int a = 2 * j, b = a + 1;
                    unsigned ia = (ipack[j] >> 0) & 0xFFFFu;
                    unsigned ib = (ipack[j] >> 16) & 0xFFFFu;
                    bool c = (dmin[a] > dmin[b]) || (dmin[a] == dmin[b] && ia < ib);
                    nd[j] = c ? dmin[a] : dmin[b];
                    ni[j] = c ? ia : ib;
                    nk[j] = c ? a : b;
                }
#pragma unroll
                for (int lvl = 4; lvl >= 1; lvl >>= 1) {
                    for (int j = 0; j < lvl; j++) {
                        int a = 2 * j, b = a + 1;
                        bool c = (nd[a] > nd[b]) || (nd[a] == nd[b] && ni[a] < ni[b]);
                        nd[j] = c ? nd[a] : nd[b];
                        ni[j] = c ? ni[a] : ni[b];
                        nk[j] = c ? nk[a] : nk[b];
                    }
                }
                cval = __float_as_uint(nd[0]);
                cidx = ni[0];
                ckp = nk[0];
            }
            unsigned vmax = redux_max_u32(cval);
            unsigned imin = redux_min_u32((cval == vmax) ? cidx : 0xFFFFFFFFu);
            if (cval == vmax && cidx == imin) {   // unique winner lane
                float2 xy = s_xy[ckp * 1024 + tid];
                float zz = s_z[ckp * 1024 + tid];
                s_wp[w] = make_float4(__uint_as_float(vmax),
                                      __uint_as_float(0xFFFFFFFFu - imin),
                                      xy.x, xy.y);
                s_wz[w] = zz;
            }
        }

        if (w == 0) {
            NBAR_SYNC(1);                       // wait: all workers published (drains STS)
            float4 pv = s_wp[lane];
            float  pz = s_wz[lane];
            unsigned hi = __float_as_uint(pv.x);
            unsigned lo = __float_as_uint(pv.y);
            unsigned vmax = redux_max_u32(hi);
            unsigned lomax = redux_max_u32((hi == vmax) ? lo : 0u);
            bool win = (hi == vmax && lo == lomax);
            unsigned bal = __ballot_sync(0xffffffffu, win);
            int jstar = __ffs(bal) - 1;
            if (win) g_idx[it] = (int)(0xFFFFFFFFu - lomax);
            float nqx = __shfl_sync(0xffffffffu, pv.z, jstar);
            float nqy = __shfl_sync(0xffffffffu, pv.w, jstar);
            float nqz = __shfl_sync(0xffffffffu, pz, jstar);
            if (lane == 0) s_bq[0] = make_float4(nqx, nqy, nqz, 0.f);
            NBAR_ARRIVE(2);                     // release workers
            qx = nqx; qy = nqy; qz = nqz;       // keep q in registers, overlap next part
        } else {
            NBAR_ARRIVE(1);                     // non-blocking
            NBAR_SYNC(2);                       // wait: q published (drains warp0's STS)
            float4 qv = s_bq[0];
            qx = qv.x; qy = qv.y; qz = qv.z;
        }
    }
    __syncthreads();
    for (int i = tid; i < MPTS; i += 1024)
        g_np[i] = g_pw[g_idx[i]];
}

// ---------------- kernel 5: top-16 KNN ----------------
__global__ void __launch_bounds__(256) k_knn()
{
    __shared__ float sd[256 * 17];
    __shared__ int   sii[256 * 17];
    int lane = threadIdx.x & 31;
    int part = threadIdx.x >> 5;
    int q = blockIdx.x * 32 + lane;
    float4 nq = __ldg(&g_np[q]);

    float bd[16]; int bi[16];
#pragma unroll
    for (int k = 0; k < 16; k++) { bd[k] = 3.4e38f; bi[k] = 0x7fffffff; }
    float wmax = 3.4e38f; int wpos = 0, widx = 0x7fffffff;

    int j0 = part * 2048;
    for (int j = j0; j < j0 + 2048; ++j) {
        float4 c = __ldg(&g_pw[j]);
        float dot = dot3_fma(nq.x, nq.y, nq.z, c.x, c.y, c.z);
        float d = sqdist_expand(nq.w, dot, c.w);
        if (d < wmax || (d == wmax && j < widx)) {
            bd[wpos] = d; bi[wpos] = j;
            wmax = -1.f; widx = -1;
#pragma unroll
            for (int k = 0; k < 16; k++)
                if (bd[k] > wmax || (bd[k] == wmax && bi[k] > widx)) {
                    wmax = bd[k]; widx = bi[k]; wpos = k;
                }
        }
    }
    int sb = threadIdx.x * 17;
#pragma unroll
    for (int k = 0; k < 16; k++) { sd[sb + k] = bd[k]; sii[sb + k] = bi[k]; }
    __syncthreads();

    if (part == 0) {
#pragma unroll 1
        for (int s = 0; s < 16; s++) {
            float md = 3.5e38f; int mi = 0x7fffffff; int mloc = 0;
            for (int src = 0; src < 8; src++) {
                int tb = (src * 32 + lane) * 17;
#pragma unroll
                for (int e = 0; e < 16; e++) {
                    float dd = sd[tb + e]; int ii = sii[tb + e];
                    if (dd < md || (dd == md && ii < mi)) { md = dd; mi = ii; mloc = tb + e; }
                }
            }
            g_knn[q * 16 + s] = mi;
            sd[mloc] = 3.6e38f;
        }
    }
}

// ---------------- kernel 6: grouped conv + maxpool ----------------
__global__ void __launch_bounds__(64) k_group(
    const float* __restrict__ p, const float* __restrict__ wd,
    const float* __restrict__ gd, const float* __restrict__ bd_,
    const float* __restrict__ md, const float* __restrict__ vd)
{
    __shared__ float fs[16 * 35];
    int q = blockIdx.x;
    int c = threadIdx.x;
    float4 nq = __ldg(&g_np[q]);

    for (int e = c; e < 16 * 35; e += 64) {
        int k = e / 35, i = e - 35 * k;
        int j = __ldg(&g_knn[q * 16 + k]);
        float v;
        if (i < 3) {
            float qq = (i == 0) ? nq.x : (i == 1) ? nq.y : nq.z;
            v = __ldg(&p[j * 3 + i]) - qq;
        } else {
            v = g_x1[j * 32 + (i - 3)];
        }
        fs[e] = v;
    }
    __syncthreads();

    float s  = __ldg(&gd[c]) / sqrtf(__ldg(&vd[c]) + 1e-5f);
    float mm = __ldg(&md[c]);
    float bb = __ldg(&bd_[c]);
    float mx = -3.4e38f;
#pragma unroll 1
    for (int k = 0; k < 16; k++) {
        float acc = 0.f;
#pragma unroll
        for (int i = 0; i < 35; i++)
            acc = fmaf(fs[k * 35 + i], __ldg(&wd[i * 64 + c]), acc);
        float h = fmaxf((acc - mm) * s + bb, 0.f);
        mx = fmaxf(mx, h);
    }
    g_x2[q * 64 + c] = mx;
}

// ---------------- kernel 7: f2 ----------------
__global__ void __launch_bounds__(256) k_f2(
    const float* __restrict__ w2, const float* __restrict__ b2,
    const float* __restrict__ g2, const float* __restrict__ bb2,
    const float* __restrict__ m2, const float* __restrict__ v2)
{
    int t = blockIdx.x * blockDim.x + threadIdx.x;
    int m = t >> 5, c = t & 31;
    float acc = __ldg(&b2[c]);
#pragma unroll 8
    for (int i = 0; i < 64; i++)
        acc = fmaf(g_x2[m * 64 + i], __ldg(&w2[i * 32 + c]), acc);
    float s = __ldg(&g2[c]) / sqrtf(__ldg(&v2[c]) + 1e-5f);
    float f = (acc - __ldg(&m2[c])) * s + __ldg(&bb2[c]);
    g_f2[t] = fmaxf(f, 0.f);
}

// ---------------- kernel 8: 3-NN interpolation ----------------
__global__ void __launch_bounds__(128) k_interp(float* __restrict__ out)
{
    int pt = blockIdx.x * 128 + threadIdx.x;
    float4 qp = g_pw[pt];

    float d0 = 3.4e38f, d1 = 3.4e38f, d2 = 3.4e38f;
    int   i0 = 0x7ffffffe, i1 = 0x7ffffffe, i2 = 0x7ffffffe;
    for (int j = 0; j < MPTS; ++j) {
        float4 c = __ldg(&g_np[j]);
        float dot = dot3_fma(qp.x, qp.y, qp.z, c.x, c.y, c.z);
        float d = sqdist_expand(qp.w, dot, c.w);
        if (d < d2 || (d == d2 && j < i2)) {
            if (d < d1 || (d == d1 && j < i1)) {
                d2 = d1; i2 = i1;
                if (d < d0 || (d == d0 && j < i0)) { d1 = d0; i1 = i0; d0 = d; i0 = j; }
                else { d1 = d; i1 = j; }
            } else { d2 = d; i2 = j; }
        }
    }
    float w0 = 1.f / (sqrtf(fmaxf(d0, 0.f)) + 1e-8f);
    float w1 = 1.f / (sqrtf(fmaxf(d1, 0.f)) + 1e-8f);
    float w2 = 1.f / (sqrtf(fmaxf(d2, 0.f)) + 1e-8f);
    float ws = w0 + w1 + w2;
    w0 /= ws; w1 /= ws; w2 /= ws;

#pragma unroll
    for (int c = 0; c < 32; c++) {
        float v = g_f2[i0 * 32 + c] * w0 + g_f2[i1 * 32 + c] * w1 + g_f2[i2 * 32 + c] * w2;
        out[pt * 32 + c] += v;
    }
}

// ---------------- launch ----------------
extern "C" void kernel_launch(void* const* d_in, const int* in_sizes, int n_in,
                              void* d_out, int out_size)
{
    const float* p    = (const float*)d_in[0];
    const float* x    = (const float*)d_in[1];
    const float* w0   = (const float*)d_in[2];
    const float* bn0g = (const float*)d_in[3];
    const float* bn0b = (const float*)d_in[4];
    const float* bn0m = (const float*)d_in[5];
    const float* bn0v = (const float*)d_in[6];
    const float* wd   = (const float*)d_in[7];
    const float* bndg = (const float*)d_in[8];
    const float* bndb = (const float*)d_in[9];
    const float* bndm = (const float*)d_in[10];
    const float* bndv = (const float*)d_in[11];
    const float* w1   = (const float*)d_in[12];
    const float* b1   = (const float*)d_in[13];
    const float* bn1g = (const float*)d_in[14];
    const float* bn1b = (const float*)d_in[15];
    const float* bn1m = (const float*)d_in[16];
    const float* bn1v = (const float*)d_in[17];
    const float* w2   = (const float*)d_in[18];
    const float* b2   = (const float*)d_in[19];
    const float* bn2g = (const float*)d_in[20];
    const float* bn2b = (const float*)d_in[21];
    const float* bn2m = (const float*)d_in[22];
    const float* bn2v = (const float*)d_in[23];
    float* out = (float*)d_out;

    cudaFuncSetAttribute(k_fps14, cudaFuncAttributeMaxDynamicSharedMemorySize, FPS_SMEM);

    k_pre<<<NPTS / 8, 256>>>(p, x, w0, bn0g, bn0b, bn0m, bn0v,
                             w1, b1, bn1g, bn1b, bn1m, bn1v, out);
    k_sortA<<<1, 1024>>>();
    k_sortB<<<NPTS / 256, 256>>>();
    k_fps14<<<1, 1024, FPS_SMEM>>>();           // launch #4 -> ncu capture slot
    k_knn<<<MPTS / 32, 256>>>();
    k_group<<<MPTS, 64>>>(p, wd, bndg, bndb, bndm, bndv);
    k_f2<<<MPTS * 32 / 256, 256>>>(w2, b2, bn2g, bn2b, bn2m, bn2v);
    k_interp<<<NPTS / 128, 128>>>(out);
}